// round 6
// baseline (speedup 1.0000x reference)
#include <cuda_runtime.h>
#include <cuda_bf16.h>
#include <cstddef>
#include <cstdint>

// Problem constants
#define BB   4
#define PP   1024
#define DD   1024
#define HH   16
#define DQK  64
#define DV   64
#define DMID 4096
#define EPS  1e-5f

// ---------------------------------------------------------------------------
// Scratch layout (floats). Y aliases XR (xr dead after QKV projections).
// ---------------------------------------------------------------------------
__device__ float g_scratch[132120576];

#define OFF_XR     0            //  4,194,304
#define OFF_WQ     4194304      //  1,048,576
#define OFF_WK     5242880      //  1,048,576
#define OFF_WV     6291456      //  1,048,576
#define OFF_WPV    7340032      //  1,048,576
#define OFF_W1R    8388608      //  4,194,304
#define OFF_W2R    12582912     //  2,097,152
#define OFF_QB     14680064     //  4,194,304
#define OFF_KB     18874368     //  4,194,304
#define OFF_VB     23068672     //  4,194,304
#define OFF_SC     27262976     // 67,108,864
#define OFF_O      94371840     //  4,194,304
#define OFF_XSA    98566144     //  4,194,304
#define OFF_X1     102760448    //  4,194,304
#define OFF_H      106954752    // 16,777,216
#define OFF_T      123731968    //  8,388,608
#define OFF_Y      OFF_XR       //  alias

// ---------------------------------------------------------------------------
// PTX helpers
// ---------------------------------------------------------------------------
__device__ __forceinline__ uint32_t smem_u32(const void* p) {
    return (uint32_t)__cvta_generic_to_shared(p);
}
__device__ __forceinline__ void cp_async16(uint32_t dst, const float* src) {
    asm volatile("cp.async.cg.shared.global [%0], [%1], 16;\n" :: "r"(dst), "l"(src));
}
__device__ __forceinline__ void cp_commit() {
    asm volatile("cp.async.commit_group;\n");
}
template <int N>
__device__ __forceinline__ void cp_wait() {
    asm volatile("cp.async.wait_group %0;\n" :: "n"(N));
}
__device__ __forceinline__ uint32_t f2tf32(float f) {
    uint32_t r;
    asm("cvt.rna.tf32.f32 %0, %1;\n" : "=r"(r) : "f"(f));
    return r;
}
__device__ __forceinline__ float tf32r(float f) {
    return __uint_as_float(f2tf32(f));
}
__device__ __forceinline__ void mma_tf32(float& c0, float& c1, float& c2, float& c3,
                                         uint32_t a0, uint32_t a1, uint32_t a2, uint32_t a3,
                                         uint32_t b0, uint32_t b1) {
    asm volatile(
        "mma.sync.aligned.m16n8k8.row.col.f32.tf32.tf32.f32 "
        "{%0,%1,%2,%3},{%4,%5,%6,%7},{%8,%9},{%0,%1,%2,%3};\n"
        : "+f"(c0), "+f"(c1), "+f"(c2), "+f"(c3)
        : "r"(a0), "r"(a1), "r"(a2), "r"(a3), "r"(b0), "r"(b1));
}

// ---------------------------------------------------------------------------
// Prep: round-to-tf32 copy
// ---------------------------------------------------------------------------
__global__ __launch_bounds__(256)
void round_copy_kernel(const float* __restrict__ src, float* __restrict__ dst)
{
    const int i = blockIdx.x * 256 + threadIdx.x;
    const float4 v = ((const float4*)src)[i];
    float4 o;
    o.x = tf32r(v.x); o.y = tf32r(v.y); o.z = tf32r(v.z); o.w = tf32r(v.w);
    ((float4*)dst)[i] = o;
}

// ---------------------------------------------------------------------------
// BIG TF32 GEMM (NT only): C = alpha * A @ B^T + bias
// CTA tile 256x128x32, warp tile 64x64, 8 warps, 3-stage cp.async.
// B must be pre-rounded to tf32; CVTA rounds A fragments at use.
// EPI = 0: plain; EPI = 1: output rounded to tf32.
// ---------------------------------------------------------------------------
template <int EPI, bool CVTA>
__global__ __launch_bounds__(256, 1)
void tgemm_big(const float* __restrict__ A, const float* __restrict__ B,
               const float* __restrict__ bias, float* __restrict__ C,
               int M, int N, int K, int lda, int ldb, int ldc,
               int div,
               long long aOuter, long long aInner,
               long long bOuter, long long bInner,
               long long cOuter, long long cInner,
               float alpha)
{
    constexpr int BM = 256;
    constexpr int BN = 128;
    constexpr int BK = 32;
    constexpr int STAGES = 3;
    constexpr int ASZ = BM * BK;   // 8192 floats
    constexpr int BSZ = BN * BK;   // 4096 floats

    const int z = blockIdx.z;
    A += (long long)(z / div) * aOuter + (long long)(z % div) * aInner;
    B += (long long)(z / div) * bOuter + (long long)(z % div) * bInner;
    C += (long long)(z / div) * cOuter + (long long)(z % div) * cInner;

    extern __shared__ float sm[];
    float* Asm = sm;                   // [STAGES][ASZ]
    float* Bsm = sm + STAGES * ASZ;    // [STAGES][BSZ]

    const int tid  = threadIdx.x;
    const int lane = tid & 31;
    const int warp = tid >> 5;
    const int warp_m = (warp >> 1) * 64;
    const int warp_n = (warp & 1) * 64;
    const int m0 = blockIdx.y * BM;
    const int n0 = blockIdx.x * BN;
    const int Kiters = K / BK;

    const uint32_t a_base = smem_u32(Asm);
    const uint32_t b_base = smem_u32(Bsm);

    auto issue_stage = [&](int it) {
        if (it < Kiters) {
            const int s  = it % STAGES;
            const int k0 = it * BK;
            // A: 256x32 = 2048 f4, 8 per thread
#pragma unroll
            for (int i = 0; i < 8; i++) {
                const int idx = tid + i * 256;
                const int r = idx >> 3;
                const int g = idx & 7;
                const float* src = A + (size_t)(m0 + r) * lda + k0 + g * 4;
                cp_async16(a_base + (uint32_t)(s * ASZ + (r * 8 + (g ^ (r & 7))) * 4) * 4, src);
            }
            // B^T: 128x32 = 1024 f4, 4 per thread
#pragma unroll
            for (int i = 0; i < 4; i++) {
                const int idx = tid + i * 256;
                const int r = idx >> 3;
                const int g = idx & 7;
                const float* src = B + (size_t)(n0 + r) * ldb + k0 + g * 4;
                cp_async16(b_base + (uint32_t)(s * BSZ + (r * 8 + (g ^ (r & 7))) * 4) * 4, src);
            }
        }
        cp_commit();
    };

    float acc[4][8][4];
#pragma unroll
    for (int mi = 0; mi < 4; mi++)
#pragma unroll
        for (int nj = 0; nj < 8; nj++)
#pragma unroll
            for (int c = 0; c < 4; c++) acc[mi][nj][c] = 0.f;

    issue_stage(0);
    issue_stage(1);

    const int e = lane & 3;
    const int qd = lane >> 2;

    for (int it = 0; it < Kiters; ++it) {
        cp_wait<1>();
        __syncthreads();
        issue_stage(it + 2);

        const float* as = Asm + (it % STAGES) * ASZ;
        const float* bs = Bsm + (it % STAGES) * BSZ;

#pragma unroll
        for (int ks = 0; ks < 4; ks++) {
            const int g0 = ks * 2, g1 = ks * 2 + 1;
            uint32_t af[4][4];
#pragma unroll
            for (int mi = 0; mi < 4; mi++) {
                const int r0 = warp_m + mi * 16 + qd;
                const int r1 = r0 + 8;
                const float v0 = as[r0 * 32 + ((g0 ^ (r0 & 7)) << 2) + e];
                const float v1 = as[r1 * 32 + ((g0 ^ (r1 & 7)) << 2) + e];
                const float v2 = as[r0 * 32 + ((g1 ^ (r0 & 7)) << 2) + e];
                const float v3 = as[r1 * 32 + ((g1 ^ (r1 & 7)) << 2) + e];
                if (CVTA) {
                    af[mi][0] = f2tf32(v0); af[mi][1] = f2tf32(v1);
                    af[mi][2] = f2tf32(v2); af[mi][3] = f2tf32(v3);
                } else {
                    af[mi][0] = __float_as_uint(v0); af[mi][1] = __float_as_uint(v1);
                    af[mi][2] = __float_as_uint(v2); af[mi][3] = __float_as_uint(v3);
                }
            }
            uint32_t bf[8][2];
#pragma unroll
            for (int nj = 0; nj < 8; nj++) {
                const int r = warp_n + nj * 8 + qd;
                bf[nj][0] = __float_as_uint(bs[r * 32 + ((g0 ^ (r & 7)) << 2) + e]);
                bf[nj][1] = __float_as_uint(bs[r * 32 + ((g1 ^ (r & 7)) << 2) + e]);
            }
#pragma unroll
            for (int mi = 0; mi < 4; mi++)
#pragma unroll
                for (int nj = 0; nj < 8; nj++)
                    mma_tf32(acc[mi][nj][0], acc[mi][nj][1], acc[mi][nj][2], acc[mi][nj][3],
                             af[mi][0], af[mi][1], af[mi][2], af[mi][3],
                             bf[nj][0], bf[nj][1]);
        }
        __syncthreads();
    }

    // ---- epilogue ----
#pragma unroll
    for (int mi = 0; mi < 4; mi++) {
#pragma unroll
        for (int nj = 0; nj < 8; nj++) {
            const int row0 = m0 + warp_m + mi * 16 + qd;
            const int col  = n0 + warp_n + nj * 8 + e * 2;
            float2 v0, v1;
            v0.x = acc[mi][nj][0] * alpha;
            v0.y = acc[mi][nj][1] * alpha;
            v1.x = acc[mi][nj][2] * alpha;
            v1.y = acc[mi][nj][3] * alpha;
            if (bias) {
                const float b0 = bias[col], b1 = bias[col + 1];
                v0.x += b0; v0.y += b1;
                v1.x += b0; v1.y += b1;
            }
            if (EPI == 1) {
                v0.x = tf32r(v0.x); v0.y = tf32r(v0.y);
                v1.x = tf32r(v1.x); v1.y = tf32r(v1.y);
            }
            *(float2*)&C[(size_t)row0 * ldc + col] = v0;
            *(float2*)&C[(size_t)(row0 + 8) * ldc + col] = v1;
        }
    }
}

// ---------------------------------------------------------------------------
// 128x64 NN GEMM (PV only): C = A @ B, attn CVTA, output rounded. (R5 proven)
// ---------------------------------------------------------------------------
__global__ __launch_bounds__(256, 2)
void tgemm_pv(const float* __restrict__ A, const float* __restrict__ B,
              float* __restrict__ C,
              int K, int lda, int ldb, int ldc,
              int div,
              long long aOuter, long long aInner,
              long long bOuter, long long bInner,
              long long cOuter, long long cInner)
{
    constexpr int BM = 128;
    constexpr int BN = 64;
    constexpr int BK = 32;
    constexpr int STAGES = 3;
    constexpr int NT = (BN / 2) / 8;
    constexpr int ASZ = BM * BK;
    constexpr int LDB_S = BN + 8;
    constexpr int BSZ = BK * LDB_S;

    const int z = blockIdx.z;
    A += (long long)(z / div) * aOuter + (long long)(z % div) * aInner;
    B += (long long)(z / div) * bOuter + (long long)(z % div) * bInner;
    C += (long long)(z / div) * cOuter + (long long)(z % div) * cInner;

    extern __shared__ float sm[];
    float* Asm = sm;
    float* Bsm = sm + STAGES * ASZ;

    const int tid  = threadIdx.x;
    const int lane = tid & 31;
    const int warp = tid >> 5;
    const int warp_m = (warp >> 1) * 32;
    const int warp_n = (warp & 1) * (BN / 2);
    const int m0 = blockIdx.y * BM;
    const int n0 = blockIdx.x * BN;
    const int Kiters = K / BK;

    const uint32_t a_base = smem_u32(Asm);
    const uint32_t b_base = smem_u32(Bsm);

    auto issue_stage = [&](int it) {
        if (it < Kiters) {
            const int s  = it % STAGES;
            const int k0 = it * BK;
#pragma unroll
            for (int i = 0; i < 4; i++) {
                const int idx = tid + i * 256;
                const int r = idx >> 3;
                const int g = idx & 7;
                const float* src = A + (size_t)(m0 + r) * lda + k0 + g * 4;
                cp_async16(a_base + (uint32_t)(s * ASZ + (r * 8 + (g ^ (r & 7))) * 4) * 4, src);
            }
#pragma unroll
            for (int i = 0; i < BN / 32; i++) {
                const int idx = tid + i * 256;
                const int r = idx / (BN / 4);
                const int g = idx % (BN / 4);
                const float* src = B + (size_t)(k0 + r) * ldb + n0 + g * 4;
                cp_async16(b_base + (uint32_t)(s * BSZ + r * LDB_S + g * 4) * 4, src);
            }
        }
        cp_commit();
    };

    float acc[2][NT][4];
#pragma unroll
    for (int mi = 0; mi < 2; mi++)
#pragma unroll
        for (int nj = 0; nj < NT; nj++)
#pragma unroll
            for (int c = 0; c < 4; c++) acc[mi][nj][c] = 0.f;

    issue_stage(0);
    issue_stage(1);

    const int e = lane & 3;
    const int qd = lane >> 2;

    for (int it = 0; it < Kiters; ++it) {
        cp_wait<1>();
        __syncthreads();
        issue_stage(it + 2);

        const float* as = Asm + (it % STAGES) * ASZ;
        const float* bs = Bsm + (it % STAGES) * BSZ;

#pragma unroll
        for (int ks = 0; ks < 4; ks++) {
            const int g0 = ks * 2, g1 = ks * 2 + 1;
            uint32_t af[2][4];
#pragma unroll
            for (int mi = 0; mi < 2; mi++) {
                const int r0 = warp_m + mi * 16 + qd;
                const int r1 = r0 + 8;
                af[mi][0] = f2tf32(as[r0 * 32 + ((g0 ^ (r0 & 7)) << 2) + e]);
                af[mi][1] = f2tf32(as[r1 * 32 + ((g0 ^ (r1 & 7)) << 2) + e]);
                af[mi][2] = f2tf32(as[r0 * 32 + ((g1 ^ (r0 & 7)) << 2) + e]);
                af[mi][3] = f2tf32(as[r1 * 32 + ((g1 ^ (r1 & 7)) << 2) + e]);
            }
            uint32_t bf[NT][2];
#pragma unroll
            for (int nj = 0; nj < NT; nj++) {
                const int n = warp_n + nj * 8 + qd;
                bf[nj][0] = __float_as_uint(bs[(ks * 8 + e) * LDB_S + n]);
                bf[nj][1] = __float_as_uint(bs[(ks * 8 + e + 4) * LDB_S + n]);
            }
#pragma unroll
            for (int mi = 0; mi < 2; mi++)
#pragma unroll
                for (int nj = 0; nj < NT; nj++)
                    mma_tf32(acc[mi][nj][0], acc[mi][nj][1], acc[mi][nj][2], acc[mi][nj][3],
                             af[mi][0], af[mi][1], af[mi][2], af[mi][3],
                             bf[nj][0], bf[nj][1]);
        }
        __syncthreads();
    }

#pragma unroll
    for (int mi = 0; mi < 2; mi++) {
#pragma unroll
        for (int nj = 0; nj < NT; nj++) {
            const int row0 = m0 + warp_m + mi * 16 + qd;
            const int col  = n0 + warp_n + nj * 8 + e * 2;
            float2 v0, v1;
            v0.x = tf32r(acc[mi][nj][0]);
            v0.y = tf32r(acc[mi][nj][1]);
            v1.x = tf32r(acc[mi][nj][2]);
            v1.y = tf32r(acc[mi][nj][3]);
            *(float2*)&C[(size_t)row0 * ldc + col] = v0;
            *(float2*)&C[(size_t)(row0 + 8) * ldc + col] = v1;
        }
    }
}

// ---------------------------------------------------------------------------
// Head-mix + attn_prev + softmax. One CTA per (b, q). (R3 verbatim)
// ---------------------------------------------------------------------------
#define MIX_SMEM_BYTES ((16 * 1024 + 256 + 8) * 4)

__global__ __launch_bounds__(256)
void mix_softmax_kernel(const float* __restrict__ scores,
                        const float* __restrict__ attn_prev,
                        const float* __restrict__ W_th,
                        float* __restrict__ attn)
{
    extern __shared__ float sh[];
    float* s_sc  = sh;
    float* s_w   = sh + 16 * 1024;
    float* s_red = s_w + 256;

    const int tid = threadIdx.x;
    const int bq  = blockIdx.x;
    const int b   = bq >> 10;
    const int q   = bq & 1023;
    const int lane = tid & 31;
    const int warp = tid >> 5;

#pragma unroll
    for (int h = 0; h < 16; h++) {
        const float4* src =
            (const float4*)(scores + ((size_t)(b * 16 + h) * 1024 + q) * 1024);
        ((float4*)(s_sc + h * 1024))[tid] = src[tid];
    }
    if (tid < 256) s_w[tid] = W_th[tid];
    __syncthreads();

    for (int g = 0; g < 16; g++) {
        const size_t rowbase = ((size_t)(b * 16 + g) * 1024 + q) * 1024;
        const float* prev = attn_prev + rowbase;
        float* dst = attn + rowbase;

        float vals[4];
        float mx = -1e30f;
#pragma unroll
        for (int i = 0; i < 4; i++) {
            const int k = tid + i * 256;
            float acc = prev[k];
#pragma unroll
            for (int h = 0; h < 16; h++)
                acc = fmaf(s_w[g * 16 + h], s_sc[h * 1024 + k], acc);
            vals[i] = acc;
            mx = fmaxf(mx, acc);
        }
#pragma unroll
        for (int o = 16; o; o >>= 1)
            mx = fmaxf(mx, __shfl_xor_sync(0xffffffffu, mx, o));
        if (lane == 0) s_red[warp] = mx;
        __syncthreads();
        float m = s_red[0];
#pragma unroll
        for (int w = 1; w < 8; w++) m = fmaxf(m, s_red[w]);
        __syncthreads();

        float sum = 0.f;
#pragma unroll
        for (int i = 0; i < 4; i++) {
            vals[i] = __expf(vals[i] - m);
            sum += vals[i];
        }
#pragma unroll
        for (int o = 16; o; o >>= 1)
            sum += __shfl_xor_sync(0xffffffffu, sum, o);
        if (lane == 0) s_red[warp] = sum;
        __syncthreads();
        float tot = 0.f;
#pragma unroll
        for (int w = 0; w < 8; w++) tot += s_red[w];
        const float inv = 1.0f / tot;
#pragma unroll
        for (int i = 0; i < 4; i++) dst[tid + i * 256] = vals[i] * inv;
        __syncthreads();
    }
}

// ---------------------------------------------------------------------------
// out = LayerNorm(a + b) * gamma + beta, rows of 1024. (R3 verbatim)
// ---------------------------------------------------------------------------
__global__ __launch_bounds__(256)
void add_ln_kernel(const float* __restrict__ a, const float* __restrict__ b,
                   const float* __restrict__ gam, const float* __restrict__ bet,
                   float* __restrict__ out)
{
    __shared__ float s_red[8];
    __shared__ float s_red2[8];
    const int row = blockIdx.x;
    const int tid = threadIdx.x;
    const int lane = tid & 31, warp = tid >> 5;

    const float4 va = ((const float4*)(a + (size_t)row * 1024))[tid];
    const float4 vb = ((const float4*)(b + (size_t)row * 1024))[tid];
    float4 v;
    v.x = va.x + vb.x; v.y = va.y + vb.y; v.z = va.z + vb.z; v.w = va.w + vb.w;

    float s  = v.x + v.y + v.z + v.w;
    float s2 = v.x * v.x + v.y * v.y + v.z * v.z + v.w * v.w;
#pragma unroll
    for (int o = 16; o; o >>= 1) {
        s  += __shfl_xor_sync(0xffffffffu, s, o);
        s2 += __shfl_xor_sync(0xffffffffu, s2, o);
    }
    if (lane == 0) { s_red[warp] = s; s_red2[warp] = s2; }
    __syncthreads();
    float ts = 0.f, ts2 = 0.f;
#pragma unroll
    for (int w = 0; w < 8; w++) { ts += s_red[w]; ts2 += s_red2[w]; }

    const float mu  = ts * (1.0f / 1024.0f);
    const float var = ts2 * (1.0f / 1024.0f) - mu * mu;
    const float inv = rsqrtf(var + EPS);

    const float4 g4 = ((const float4*)gam)[tid];
    const float4 b4 = ((const float4*)bet)[tid];
    float4 o;
    o.x = (v.x - mu) * inv * g4.x + b4.x;
    o.y = (v.y - mu) * inv * g4.y + b4.y;
    o.z = (v.z - mu) * inv * g4.z + b4.z;
    o.w = (v.w - mu) * inv * g4.w + b4.w;
    ((float4*)(out + (size_t)row * 1024))[tid] = o;
}

// ---------------------------------------------------------------------------
// GLU: t[r, j] = h[r, j] * relu(h[r, 2048 + j]) (R3 verbatim)
// ---------------------------------------------------------------------------
__global__ __launch_bounds__(256)
void glu_kernel(const float* __restrict__ h, float* __restrict__ t)
{
    const int i = blockIdx.x * blockDim.x + threadIdx.x;
    const int r = i >> 9;
    const int j = i & 511;
    const float4* hr = (const float4*)(h + (size_t)r * 4096);
    const float4 a = hr[j];
    const float4 g = hr[512 + j];
    float4 o;
    o.x = a.x * fmaxf(g.x, 0.f);
    o.y = a.y * fmaxf(g.y, 0.f);
    o.z = a.z * fmaxf(g.z, 0.f);
    o.w = a.w * fmaxf(g.w, 0.f);
    ((float4*)t)[i] = o;
}

// ---------------------------------------------------------------------------
// Launcher
// ---------------------------------------------------------------------------
extern "C" void kernel_launch(void* const* d_in, const int* in_sizes, int n_in,
                              void* d_out, int out_size)
{
    const float* x         = (const float*)d_in[0];
    const float* attn_prev = (const float*)d_in[1];
    const float* Wq        = (const float*)d_in[2];
    const float* Wk        = (const float*)d_in[3];
    const float* Wv        = (const float*)d_in[4];
    const float* W_th      = (const float*)d_in[5];
    const float* Wpv       = (const float*)d_in[6];
    const float* W1        = (const float*)d_in[7];
    const float* b1        = (const float*)d_in[8];
    const float* W2        = (const float*)d_in[9];
    const float* b2        = (const float*)d_in[10];
    const float* ln1g      = (const float*)d_in[11];
    const float* ln1b      = (const float*)d_in[12];
    const float* ln2g      = (const float*)d_in[13];
    const float* ln2b      = (const float*)d_in[14];

    float* out  = (float*)d_out;
    float* attn = out + (size_t)BB * PP * DD;

    float* s = nullptr;
    cudaGetSymbolAddress((void**)&s, g_scratch);
    float* xr   = s + OFF_XR;
    float* wqr  = s + OFF_WQ;
    float* wkr  = s + OFF_WK;
    float* wvr  = s + OFF_WV;
    float* wpvr = s + OFF_WPV;
    float* w1r  = s + OFF_W1R;
    float* w2r  = s + OFF_W2R;
    float* qb   = s + OFF_QB;
    float* kb   = s + OFF_KB;
    float* vb   = s + OFF_VB;
    float* sc   = s + OFF_SC;
    float* ob   = s + OFF_O;
    float* xsa  = s + OFF_XSA;
    float* x1   = s + OFF_X1;
    float* hb   = s + OFF_H;
    float* tb   = s + OFF_T;
    float* yb   = s + OFF_Y;    // aliases xr (dead after QKV projections)

    const int SM_BIG = 3 * (256 * 32 + 128 * 32) * 4;          // 147456
    const int SM_NN  = 3 * (128 * 32 + 32 * (64 + 8)) * 4;     // 76800
    cudaFuncSetAttribute((const void*)tgemm_big<0, false>,
                         cudaFuncAttributeMaxDynamicSharedMemorySize, SM_BIG);
    cudaFuncSetAttribute((const void*)tgemm_big<1, false>,
                         cudaFuncAttributeMaxDynamicSharedMemorySize, SM_BIG);
    cudaFuncSetAttribute((const void*)tgemm_big<0, true>,
                         cudaFuncAttributeMaxDynamicSharedMemorySize, SM_BIG);
    cudaFuncSetAttribute((const void*)tgemm_pv,
                         cudaFuncAttributeMaxDynamicSharedMemorySize, SM_NN);
    cudaFuncSetAttribute(mix_softmax_kernel,
                         cudaFuncAttributeMaxDynamicSharedMemorySize, MIX_SMEM_BYTES);

    const int M = BB * PP;          // 4096
    const long long zero = 0;

    // ---- prep: tf32-round x + all weights ----
    round_copy_kernel<<<4096, 256>>>(x, xr);
    round_copy_kernel<<<1024, 256>>>(Wq, wqr);
    round_copy_kernel<<<1024, 256>>>(Wk, wkr);
    round_copy_kernel<<<1024, 256>>>(Wv, wvr);
    round_copy_kernel<<<1024, 256>>>(Wpv, wpvr);
    round_copy_kernel<<<4096, 256>>>(W1, w1r);
    round_copy_kernel<<<2048, 256>>>(W2, w2r);

    // 1-3: Q (alpha=0.125), K, V projections — outputs tf32-rounded
    {
        dim3 grid(DD / 128, M / 256, 1);
        tgemm_big<1, false><<<grid, 256, SM_BIG>>>(xr, wqr, nullptr, qb,
            M, HH * DQK, DD, DD, DD, HH * DQK,
            1, zero, zero, zero, zero, zero, zero, 0.125f);
        tgemm_big<1, false><<<grid, 256, SM_BIG>>>(xr, wkr, nullptr, kb,
            M, HH * DQK, DD, DD, DD, HH * DQK,
            1, zero, zero, zero, zero, zero, zero, 1.0f);
        tgemm_big<1, false><<<grid, 256, SM_BIG>>>(xr, wvr, nullptr, vb,
            M, HH * DV, DD, DD, DD, HH * DV,
            1, zero, zero, zero, zero, zero, zero, 1.0f);
    }

    // 4: scores[b,h] = q_bh @ k_bh^T  (batched over 64)
    {
        dim3 grid(PP / 128, PP / 256, BB * HH);
        tgemm_big<0, false><<<grid, 256, SM_BIG>>>(qb, kb, nullptr, sc,
            PP, PP, DQK, HH * DQK, HH * DQK, PP,
            HH,
            (long long)PP * 1024, (long long)DQK,
            (long long)PP * 1024, (long long)DQK,
            (long long)HH * PP * PP, (long long)PP * PP,
            1.0f);
    }

    // 5: head mix + attn_prev + softmax -> attn (fp32, into d_out)
    mix_softmax_kernel<<<BB * PP, 256, MIX_SMEM_BYTES>>>(sc, attn_prev, W_th, attn);

    // 6: o[b,h] = attn_bh @ v_bh  (NN, attn cvt'd in kernel; output rounded)
    {
        dim3 grid(1, PP / 128, BB * HH);
        tgemm_pv<<<grid, 256, SM_NN>>>(attn, vb, ob,
            PP, PP, HH * DV, HH * DV,
            HH,
            (long long)HH * PP * PP, (long long)PP * PP,
            (long long)PP * 1024, (long long)DV,
            (long long)PP * 1024, (long long)DV);
    }

    // 7: x_sa = o @ Wpv^T
    {
        dim3 grid(DD / 128, M / 256, 1);
        tgemm_big<0, false><<<grid, 256, SM_BIG>>>(ob, wpvr, nullptr, xsa,
            M, DD, HH * DV, HH * DV, HH * DV, DD,
            1, zero, zero, zero, zero, zero, zero, 1.0f);
    }

    // 8: x1 = LN(x + x_sa)
    add_ln_kernel<<<M, 256>>>(x, xsa, ln1g, ln1b, x1);

    // 9: h = x1 @ W1^T + b1   (x1 CVTA)
    {
        dim3 grid(DMID / 128, M / 256, 1);
        tgemm_big<0, true><<<grid, 256, SM_BIG>>>(x1, w1r, b1, hb,
            M, DMID, DD, DD, DD, DMID,
            1, zero, zero, zero, zero, zero, zero, 1.0f);
    }

    // 10: GLU -> t
    glu_kernel<<<(M * (DMID / 2) / 4) / 256, 256>>>(hb, tb);

    // 11: y = t @ W2^T + b2   (t CVTA)
    {
        dim3 grid(DD / 128, M / 256, 1);
        tgemm_big<0, true><<<grid, 256, SM_BIG>>>(tb, w2r, b2, yb,
            M, DD, DMID / 2, DMID / 2, DMID / 2, DD,
            1, zero, zero, zero, zero, zero, zero, 1.0f);
    }

    // 12: out = LN(x1 + y)
    add_ln_kernel<<<M, 256>>>(x1, yb, ln2g, ln2b, out);
}

// round 7
// speedup vs baseline: 1.4157x; 1.4157x over previous
#include <cuda_runtime.h>
#include <cuda_fp16.h>
#include <cstddef>
#include <cstdint>

// Problem constants
#define BB   4
#define PP   1024
#define DD   1024
#define HH   16
#define DQK  64
#define DV   64
#define DMID 4096
#define EPS  1e-5f

// ---------------------------------------------------------------------------
// Scratch: float region + half region (cast), no allocations.
// ---------------------------------------------------------------------------
__device__ float g_scratch[110100480];

// float region (float offsets)
#define OFF_XSA   0            // 4,194,304
#define OFF_X1    4194304      // 4,194,304
#define OFF_Y     8388608      // 4,194,304
#define HALF_BASE 12582912     // halfs start here (float offset)

// half region (half offsets from half base)
#define HO_XH     0            //  4M
#define HO_WQ     4194304      //  1M
#define HO_WK     5242880      //  1M
#define HO_WV     6291456      //  1M
#define HO_WPV    7340032      //  1M
#define HO_W1     8388608      //  4M
#define HO_W2     12582912     //  2M
#define HO_QH     14680064     //  4M
#define HO_KH     18874368     //  4M
#define HO_VT     23068672     //  4M (transposed V: per (b,h) 64x1024)
#define HO_SC     27262976     // 64M (scores, half)
#define HO_ATTNH  94371840     // 64M (attn, half copy)
#define HO_OH     161480704    //  4M
#define HO_X1H    165675008    //  4M
#define HO_HH     169869312    // 16M
#define HO_TH     186646528    //  8M
// total halfs = 195,035,136 = 97,517,568 floats; 12,582,912 + that = 110,100,480 ✓

// ---------------------------------------------------------------------------
// PTX helpers
// ---------------------------------------------------------------------------
__device__ __forceinline__ uint32_t smem_u32(const void* p) {
    return (uint32_t)__cvta_generic_to_shared(p);
}
__device__ __forceinline__ void cp_async16(uint32_t dst, const void* src) {
    asm volatile("cp.async.cg.shared.global [%0], [%1], 16;\n" :: "r"(dst), "l"(src));
}
__device__ __forceinline__ void cp_commit() {
    asm volatile("cp.async.commit_group;\n");
}
template <int N>
__device__ __forceinline__ void cp_wait() {
    asm volatile("cp.async.wait_group %0;\n" :: "n"(N));
}
__device__ __forceinline__ void mma_f16(float& c0, float& c1, float& c2, float& c3,
                                        uint32_t a0, uint32_t a1, uint32_t a2, uint32_t a3,
                                        uint32_t b0, uint32_t b1) {
    asm volatile(
        "mma.sync.aligned.m16n8k16.row.col.f32.f16.f16.f32 "
        "{%0,%1,%2,%3},{%4,%5,%6,%7},{%8,%9},{%0,%1,%2,%3};\n"
        : "+f"(c0), "+f"(c1), "+f"(c2), "+f"(c3)
        : "r"(a0), "r"(a1), "r"(a2), "r"(a3), "r"(b0), "r"(b1));
}

// ---------------------------------------------------------------------------
// Prep: float -> half copy (4 elems/thread)
// ---------------------------------------------------------------------------
__global__ __launch_bounds__(256)
void h_copy_kernel(const float* __restrict__ src, __half* __restrict__ dst)
{
    const int i = blockIdx.x * 256 + threadIdx.x;
    const float4 v = ((const float4*)src)[i];
    __half2* d = (__half2*)dst;
    d[2 * i]     = __floats2half2_rn(v.x, v.y);
    d[2 * i + 1] = __floats2half2_rn(v.z, v.w);
}

// ---------------------------------------------------------------------------
// FP16 tensor-core GEMM (NT): C = alpha * A @ B^T (+bias)
// CTA 128 x BN x 32(halfs), 3-stage cp.async, 8 warps.
// Swizzle: row r of 32 halfs = 4 x 16B chunks; chunk c stored at c^((r>>1)&3).
// EPI: 0 = float out, 1 = half out, 2 = V-transpose half out (to vt layout).
// ---------------------------------------------------------------------------
template <int BN, int EPI>
__global__ __launch_bounds__(256, 2)
void tgemm_h(const __half* __restrict__ A, const __half* __restrict__ B,
             const float* __restrict__ bias, void* __restrict__ Cv,
             int K, int lda, int ldb, int ldc,
             int div,
             long long aOuter, long long aInner,
             long long bOuter, long long bInner,
             long long cOuter, long long cInner,
             float alpha)
{
    constexpr int BM = 128;
    constexpr int STAGES = 3;
    constexpr int NJ = BN / 16;            // n-tiles per warp (warp_n span BN/2)
    constexpr int ASZ = BM * 32;           // halfs per stage
    constexpr int BSZ = BN * 32;

    const int z = blockIdx.z;
    A += (long long)(z / div) * aOuter + (long long)(z % div) * aInner;
    B += (long long)(z / div) * bOuter + (long long)(z % div) * bInner;
    const long long coff = (long long)(z / div) * cOuter + (long long)(z % div) * cInner;

    extern __shared__ __half smh[];
    __half* Asm = smh;
    __half* Bsm = smh + STAGES * ASZ;

    const int tid  = threadIdx.x;
    const int lane = tid & 31;
    const int warp = tid >> 5;
    const int warp_m = (warp >> 1) * 32;
    const int warp_n = (warp & 1) * (BN / 2);
    const int m0 = blockIdx.y * BM;
    const int n0 = blockIdx.x * BN;
    const int Kiters = K / 32;

    const uint32_t a_base = smem_u32(Asm);
    const uint32_t b_base = smem_u32(Bsm);

    auto issue_stage = [&](int it) {
        if (it < Kiters) {
            const int s  = it % STAGES;
            const int k0 = it * 32;
            // A: 128 rows x 4 chunks = 512 chunks, 2/thread
#pragma unroll
            for (int i = 0; i < 2; i++) {
                const int idx = tid + i * 256;
                const int r = idx >> 2;
                const int c = idx & 3;
                const int cs = c ^ ((r >> 1) & 3);
                cp_async16(a_base + (uint32_t)(s * ASZ + r * 32 + cs * 8) * 2,
                           A + (size_t)(m0 + r) * lda + k0 + c * 8);
            }
            // B: BN rows x 4 chunks, BN/128 per thread
#pragma unroll
            for (int i = 0; i < BN / 64; i++) {
                const int idx = tid + i * 256;
                const int r = idx >> 2;
                const int c = idx & 3;
                const int cs = c ^ ((r >> 1) & 3);
                cp_async16(b_base + (uint32_t)(s * BSZ + r * 32 + cs * 8) * 2,
                           B + (size_t)(n0 + r) * ldb + k0 + c * 8);
            }
        }
        cp_commit();
    };

    float acc[2][NJ][4];
#pragma unroll
    for (int mi = 0; mi < 2; mi++)
#pragma unroll
        for (int nj = 0; nj < NJ; nj++)
#pragma unroll
            for (int c = 0; c < 4; c++) acc[mi][nj][c] = 0.f;

    issue_stage(0);
    issue_stage(1);

    const int e = lane & 3;
    const int qd = lane >> 2;

    for (int it = 0; it < Kiters; ++it) {
        cp_wait<1>();
        __syncthreads();
        issue_stage(it + 2);

        const uint32_t* as2 = (const uint32_t*)(Asm + (it % STAGES) * ASZ); // h2, row stride 16
        const uint32_t* bs2 = (const uint32_t*)(Bsm + (it % STAGES) * BSZ);

#pragma unroll
        for (int ks = 0; ks < 2; ks++) {
            uint32_t af[2][4];
#pragma unroll
            for (int mi = 0; mi < 2; mi++) {
                const int r0 = warp_m + mi * 16 + qd;
                const int r1 = r0 + 8;
                const int s0 = (r0 >> 1) & 3;
                const int s1 = (r1 >> 1) & 3;
                af[mi][0] = as2[r0 * 16 + (((2 * ks)     ^ s0) << 2) + e];
                af[mi][1] = as2[r1 * 16 + (((2 * ks)     ^ s1) << 2) + e];
                af[mi][2] = as2[r0 * 16 + (((2 * ks + 1) ^ s0) << 2) + e];
                af[mi][3] = as2[r1 * 16 + (((2 * ks + 1) ^ s1) << 2) + e];
            }
            uint32_t bf[NJ][2];
#pragma unroll
            for (int nj = 0; nj < NJ; nj++) {
                const int n = warp_n + nj * 8 + qd;
                const int sn = (n >> 1) & 3;
                bf[nj][0] = bs2[n * 16 + (((2 * ks)     ^ sn) << 2) + e];
                bf[nj][1] = bs2[n * 16 + (((2 * ks + 1) ^ sn) << 2) + e];
            }
#pragma unroll
            for (int mi = 0; mi < 2; mi++)
#pragma unroll
                for (int nj = 0; nj < NJ; nj++)
                    mma_f16(acc[mi][nj][0], acc[mi][nj][1], acc[mi][nj][2], acc[mi][nj][3],
                            af[mi][0], af[mi][1], af[mi][2], af[mi][3],
                            bf[nj][0], bf[nj][1]);
        }
        __syncthreads();
    }

    // ---- epilogue ----
#pragma unroll
    for (int mi = 0; mi < 2; mi++) {
#pragma unroll
        for (int nj = 0; nj < NJ; nj++) {
            const int row0 = m0 + warp_m + mi * 16 + qd;
            const int col  = n0 + warp_n + nj * 8 + e * 2;
            float v00 = acc[mi][nj][0] * alpha;
            float v01 = acc[mi][nj][1] * alpha;
            float v10 = acc[mi][nj][2] * alpha;
            float v11 = acc[mi][nj][3] * alpha;
            if (bias) {
                const float b0 = bias[col], b1 = bias[col + 1];
                v00 += b0; v01 += b1;
                v10 += b0; v11 += b1;
            }
            if (EPI == 0) {
                float* C = (float*)Cv + coff;
                *(float2*)&C[(size_t)row0 * ldc + col] = make_float2(v00, v01);
                *(float2*)&C[(size_t)(row0 + 8) * ldc + col] = make_float2(v10, v11);
            } else if (EPI == 1) {
                __half* C = (__half*)Cv + coff;
                *(__half2*)&C[(size_t)row0 * ldc + col] = __floats2half2_rn(v00, v01);
                *(__half2*)&C[(size_t)(row0 + 8) * ldc + col] = __floats2half2_rn(v10, v11);
            } else {
                // V transpose: vt[(b*16+h)*65536 + d*1024 + t], row=token, col=h*64+d
                __half* vt = (__half*)Cv;
                const int h = col >> 6, d = col & 63;
                {
                    const int b = row0 >> 10, t = row0 & 1023;
                    __half* base = vt + (size_t)((b * 16 + h) * 65536 + (d << 10) + t);
                    base[0]    = __float2half_rn(v00);
                    base[1024] = __float2half_rn(v01);
                }
                {
                    const int r1 = row0 + 8;
                    const int b = r1 >> 10, t = r1 & 1023;
                    __half* base = vt + (size_t)((b * 16 + h) * 65536 + (d << 10) + t);
                    base[0]    = __float2half_rn(v10);
                    base[1024] = __float2half_rn(v11);
                }
            }
        }
    }
}

// ---------------------------------------------------------------------------
// Head-mix + attn_prev + softmax. One CTA per (b, q).
// scores read as half, staged to float smem; writes attn fp32 + attnh half.
// ---------------------------------------------------------------------------
#define MIX_SMEM_BYTES ((16 * 1024 + 256 + 8) * 4)

__global__ __launch_bounds__(256)
void mix_softmax_kernel(const __half* __restrict__ scores,
                        const float* __restrict__ attn_prev,
                        const float* __restrict__ W_th,
                        float* __restrict__ attn,
                        __half* __restrict__ attnh)
{
    extern __shared__ float sh[];
    float* s_sc  = sh;
    float* s_w   = sh + 16 * 1024;
    float* s_red = s_w + 256;

    const int tid = threadIdx.x;
    const int bq  = blockIdx.x;
    const int b   = bq >> 10;
    const int q   = bq & 1023;
    const int lane = tid & 31;
    const int warp = tid >> 5;

#pragma unroll
    for (int h = 0; h < 16; h++) {
        const uint2* src =
            (const uint2*)(scores + ((size_t)(b * 16 + h) * 1024 + q) * 1024);
        const uint2 pk = src[tid];
        const __half2 h0 = *(const __half2*)&pk.x;
        const __half2 h1 = *(const __half2*)&pk.y;
        const float2 f0 = __half22float2(h0);
        const float2 f1 = __half22float2(h1);
        ((float4*)(s_sc + h * 1024))[tid] = make_float4(f0.x, f0.y, f1.x, f1.y);
    }
    if (tid < 256) s_w[tid] = W_th[tid];
    __syncthreads();

    for (int g = 0; g < 16; g++) {
        const size_t rowbase = ((size_t)(b * 16 + g) * 1024 + q) * 1024;
        const float* prev = attn_prev + rowbase;
        float* dst = attn + rowbase;
        __half* dsth = attnh + rowbase;

        float vals[4];
        float mx = -1e30f;
#pragma unroll
        for (int i = 0; i < 4; i++) {
            const int k = tid + i * 256;
            float acc = prev[k];
#pragma unroll
            for (int h = 0; h < 16; h++)
                acc = fmaf(s_w[g * 16 + h], s_sc[h * 1024 + k], acc);
            vals[i] = acc;
            mx = fmaxf(mx, acc);
        }
#pragma unroll
        for (int o = 16; o; o >>= 1)
            mx = fmaxf(mx, __shfl_xor_sync(0xffffffffu, mx, o));
        if (lane == 0) s_red[warp] = mx;
        __syncthreads();
        float m = s_red[0];
#pragma unroll
        for (int w = 1; w < 8; w++) m = fmaxf(m, s_red[w]);
        __syncthreads();

        float sum = 0.f;
#pragma unroll
        for (int i = 0; i < 4; i++) {
            vals[i] = __expf(vals[i] - m);
            sum += vals[i];
        }
#pragma unroll
        for (int o = 16; o; o >>= 1)
            sum += __shfl_xor_sync(0xffffffffu, sum, o);
        if (lane == 0) s_red[warp] = sum;
        __syncthreads();
        float tot = 0.f;
#pragma unroll
        for (int w = 0; w < 8; w++) tot += s_red[w];
        const float inv = 1.0f / tot;
#pragma unroll
        for (int i = 0; i < 4; i++) {
            const float a = vals[i] * inv;
            dst[tid + i * 256] = a;
            dsth[tid + i * 256] = __float2half_rn(a);
        }
        __syncthreads();
    }
}

// ---------------------------------------------------------------------------
// out = LayerNorm(a + b)*g + beta. MODE 1: also write half copy.
// ---------------------------------------------------------------------------
template <int MODE>
__global__ __launch_bounds__(256)
void add_ln_kernel(const float* __restrict__ a, const float* __restrict__ b,
                   const float* __restrict__ gam, const float* __restrict__ bet,
                   float* __restrict__ out, __half* __restrict__ outh)
{
    __shared__ float s_red[8];
    __shared__ float s_red2[8];
    const int row = blockIdx.x;
    const int tid = threadIdx.x;
    const int lane = tid & 31, warp = tid >> 5;

    const float4 va = ((const float4*)(a + (size_t)row * 1024))[tid];
    const float4 vb = ((const float4*)(b + (size_t)row * 1024))[tid];
    float4 v;
    v.x = va.x + vb.x; v.y = va.y + vb.y; v.z = va.z + vb.z; v.w = va.w + vb.w;

    float s  = v.x + v.y + v.z + v.w;
    float s2 = v.x * v.x + v.y * v.y + v.z * v.z + v.w * v.w;
#pragma unroll
    for (int o = 16; o; o >>= 1) {
        s  += __shfl_xor_sync(0xffffffffu, s, o);
        s2 += __shfl_xor_sync(0xffffffffu, s2, o);
    }
    if (lane == 0) { s_red[warp] = s; s_red2[warp] = s2; }
    __syncthreads();
    float ts = 0.f, ts2 = 0.f;
#pragma unroll
    for (int w = 0; w < 8; w++) { ts += s_red[w]; ts2 += s_red2[w]; }

    const float mu  = ts * (1.0f / 1024.0f);
    const float var = ts2 * (1.0f / 1024.0f) - mu * mu;
    const float inv = rsqrtf(var + EPS);

    const float4 g4 = ((const float4*)gam)[tid];
    const float4 b4 = ((const float4*)bet)[tid];
    float4 o;
    o.x = (v.x - mu) * inv * g4.x + b4.x;
    o.y = (v.y - mu) * inv * g4.y + b4.y;
    o.z = (v.z - mu) * inv * g4.z + b4.z;
    o.w = (v.w - mu) * inv * g4.w + b4.w;
    ((float4*)(out + (size_t)row * 1024))[tid] = o;
    if (MODE == 1) {
        __half2* hd = (__half2*)(outh + (size_t)row * 1024);
        hd[2 * tid]     = __floats2half2_rn(o.x, o.y);
        hd[2 * tid + 1] = __floats2half2_rn(o.z, o.w);
    }
}

// ---------------------------------------------------------------------------
// GLU on half: t[r][j] = h[r][j] * relu(h[r][2048+j])
// ---------------------------------------------------------------------------
__global__ __launch_bounds__(256)
void glu_kernel(const __half* __restrict__ h, __half* __restrict__ t)
{
    const int i = blockIdx.x * 256 + threadIdx.x;  // over 4096*1024 half2
    const int r = i >> 10;
    const int j = i & 1023;
    const __half2* h2 = (const __half2*)h;
    const float2 a = __half22float2(h2[(size_t)r * 2048 + j]);
    const float2 g = __half22float2(h2[(size_t)r * 2048 + 1024 + j]);
    const float2 o = make_float2(a.x * fmaxf(g.x, 0.f), a.y * fmaxf(g.y, 0.f));
    ((__half2*)t)[(size_t)r * 1024 + j] = __floats2half2_rn(o.x, o.y);
}

// ---------------------------------------------------------------------------
// Launcher
// ---------------------------------------------------------------------------
extern "C" void kernel_launch(void* const* d_in, const int* in_sizes, int n_in,
                              void* d_out, int out_size)
{
    const float* x         = (const float*)d_in[0];
    const float* attn_prev = (const float*)d_in[1];
    const float* Wq        = (const float*)d_in[2];
    const float* Wk        = (const float*)d_in[3];
    const float* Wv        = (const float*)d_in[4];
    const float* W_th      = (const float*)d_in[5];
    const float* Wpv       = (const float*)d_in[6];
    const float* W1        = (const float*)d_in[7];
    const float* b1        = (const float*)d_in[8];
    const float* W2        = (const float*)d_in[9];
    const float* b2        = (const float*)d_in[10];
    const float* ln1g      = (const float*)d_in[11];
    const float* ln1b      = (const float*)d_in[12];
    const float* ln2g      = (const float*)d_in[13];
    const float* ln2b      = (const float*)d_in[14];

    float* out  = (float*)d_out;
    float* attn = out + (size_t)BB * PP * DD;

    float* s = nullptr;
    cudaGetSymbolAddress((void**)&s, g_scratch);
    float* xsa = s + OFF_XSA;
    float* x1  = s + OFF_X1;
    float* yb  = s + OFF_Y;
    __half* hb = (__half*)(s + HALF_BASE);
    __half* xh    = hb + HO_XH;
    __half* wqh   = hb + HO_WQ;
    __half* wkh   = hb + HO_WK;
    __half* wvh   = hb + HO_WV;
    __half* wpvh  = hb + HO_WPV;
    __half* w1h   = hb + HO_W1;
    __half* w2h   = hb + HO_W2;
    __half* qh    = hb + HO_QH;
    __half* kh    = hb + HO_KH;
    __half* vt    = hb + HO_VT;
    __half* sch   = hb + HO_SC;
    __half* attnh = hb + HO_ATTNH;
    __half* oh    = hb + HO_OH;
    __half* x1h   = hb + HO_X1H;
    __half* hh    = hb + HO_HH;
    __half* th    = hb + HO_TH;

    const int SM128 = 3 * (128 * 32 + 128 * 32) * 2;   // 49152
    const int SM64  = 3 * (128 * 32 + 64 * 32) * 2;    // 36864
    cudaFuncSetAttribute((const void*)tgemm_h<128, 0>,
                         cudaFuncAttributeMaxDynamicSharedMemorySize, SM128);
    cudaFuncSetAttribute((const void*)tgemm_h<128, 1>,
                         cudaFuncAttributeMaxDynamicSharedMemorySize, SM128);
    cudaFuncSetAttribute((const void*)tgemm_h<128, 2>,
                         cudaFuncAttributeMaxDynamicSharedMemorySize, SM128);
    cudaFuncSetAttribute((const void*)tgemm_h<64, 1>,
                         cudaFuncAttributeMaxDynamicSharedMemorySize, SM64);
    cudaFuncSetAttribute(mix_softmax_kernel,
                         cudaFuncAttributeMaxDynamicSharedMemorySize, MIX_SMEM_BYTES);

    const int M = BB * PP;          // 4096
    const long long zero = 0;

    // ---- prep: convert x + weights to half ----
    h_copy_kernel<<<4096, 256>>>(x, xh);
    h_copy_kernel<<<1024, 256>>>(Wq, wqh);
    h_copy_kernel<<<1024, 256>>>(Wk, wkh);
    h_copy_kernel<<<1024, 256>>>(Wv, wvh);
    h_copy_kernel<<<1024, 256>>>(Wpv, wpvh);
    h_copy_kernel<<<4096, 256>>>(W1, w1h);
    h_copy_kernel<<<2048, 256>>>(W2, w2h);

    // 1-3: Q (alpha=0.125) -> qh, K -> kh, V -> vt (transposed)
    {
        dim3 grid(DD / 128, M / 128, 1);
        tgemm_h<128, 1><<<grid, 256, SM128>>>(xh, wqh, nullptr, qh,
            DD, DD, DD, HH * DQK,
            1, zero, zero, zero, zero, zero, zero, 0.125f);
        tgemm_h<128, 1><<<grid, 256, SM128>>>(xh, wkh, nullptr, kh,
            DD, DD, DD, HH * DQK,
            1, zero, zero, zero, zero, zero, zero, 1.0f);
        tgemm_h<128, 2><<<grid, 256, SM128>>>(xh, wvh, nullptr, vt,
            DD, DD, DD, 0,
            1, zero, zero, zero, zero, zero, zero, 1.0f);
    }

    // 4: scores[b,h] = q_bh @ k_bh^T  -> sch (half), batched over 64
    {
        dim3 grid(PP / 128, PP / 128, BB * HH);
        tgemm_h<128, 1><<<grid, 256, SM128>>>(qh, kh, nullptr, sch,
            DQK, HH * DQK, HH * DQK, PP,
            HH,
            (long long)PP * 1024, (long long)DQK,
            (long long)PP * 1024, (long long)DQK,
            (long long)HH * PP * PP, (long long)PP * PP,
            1.0f);
    }

    // 5: mix + prev + softmax -> attn (fp32, d_out) + attnh (half)
    mix_softmax_kernel<<<BB * PP, 256, MIX_SMEM_BYTES>>>(sch, attn_prev, W_th,
                                                         attn, attnh);

    // 6: o[b,h] = attn_bh @ vt_bh^T  (NT, BN=64) -> oh (half)
    {
        dim3 grid(1, PP / 128, BB * HH);
        tgemm_h<64, 1><<<grid, 256, SM64>>>(attnh, vt, nullptr, oh,
            PP, PP, PP, HH * DV,
            HH,
            (long long)HH * PP * PP, (long long)PP * PP,
            (long long)HH * DV * PP, (long long)DV * PP,
            (long long)PP * 1024, (long long)DV,
            1.0f);
    }

    // 7: x_sa = o @ Wpv^T  -> float
    {
        dim3 grid(DD / 128, M / 128, 1);
        tgemm_h<128, 0><<<grid, 256, SM128>>>(oh, wpvh, nullptr, xsa,
            HH * DV, HH * DV, HH * DV, DD,
            1, zero, zero, zero, zero, zero, zero, 1.0f);
    }

    // 8: x1 = LN(x + xsa) -> float + half
    add_ln_kernel<1><<<M, 256>>>(x, xsa, ln1g, ln1b, x1, x1h);

    // 9: h = x1 @ W1^T + b1 -> hh (half)
    {
        dim3 grid(DMID / 128, M / 128, 1);
        tgemm_h<128, 1><<<grid, 256, SM128>>>(x1h, w1h, b1, hh,
            DD, DD, DD, DMID,
            1, zero, zero, zero, zero, zero, zero, 1.0f);
    }

    // 10: GLU -> th (half)
    glu_kernel<<<16384, 256>>>(hh, th);

    // 11: y = t @ W2^T + b2 -> float
    {
        dim3 grid(DD / 128, M / 128, 1);
        tgemm_h<128, 0><<<grid, 256, SM128>>>(th, w2h, b2, yb,
            DMID / 2, DMID / 2, DMID / 2, DD,
            1, zero, zero, zero, zero, zero, zero, 1.0f);
    }

    // 12: out = LN(x1 + y)
    add_ln_kernel<0><<<M, 256>>>(x1, yb, ln2g, ln2b, out, nullptr);
}